// round 2
// baseline (speedup 1.0000x reference)
#include <cuda_runtime.h>
#include <math.h>

// ---------------- problem constants ----------------
#define B_  8
#define T_  256
#define MEL_ 128
#define D_  192
#define NC_ 20
#define D2_ 384
#define NT_ 32     // theta updates  (chunk 8)
#define ND_ 4      // delta updates  (chunk 64)
#define EPS_ 1e-5f

// ---------------- scratch (device globals; no allocs allowed) ----------------
__device__ float g_xp [B_*T_*D_];
__device__ float g_qd [B_*T_*D_];
__device__ float g_x1 [B_*T_*D_];
__device__ float g_x2 [B_*T_*D_];
__device__ float g_h  [B_*T_*D_];
__device__ float g_g2 [B_*T_*D_];
__device__ float g_x3 [B_*T_*D_];
__device__ float g_q3 [B_*T_*D_];
__device__ float g_y  [B_*T_*D_];
__device__ float g_tmp[B_*T_*D2_];
__device__ float g_Kd [B_*ND_*D_];
__device__ float g_Vd [B_*ND_*D_];
__device__ float g_Ed [B_*ND_*D_];
__device__ float g_QKd[B_*T_*ND_];
__device__ float g_Kt [B_*NT_*D_];
__device__ float g_Vt [B_*NT_*D_];
__device__ float g_Et [B_*NT_*D_];
__device__ float g_QKt[B_*T_*NT_];
__device__ float g_pool[B_*D_];

// coefficient c_d = LR * (a^{d+1} - e^{d+1}) / (a - e), a=0.99, e=0.9
__device__ __forceinline__ void make_cd(float* cd, int n) {
    double ap = 1.0, ep = 1.0;
    for (int d = 0; d < n; d++) { ap *= 0.99; ep *= 0.9; cd[d] = (float)(0.1 * (ap - ep) / 0.09); }
}

// ---------------- tiled GEMM: C[M,N] = (res?) + A[M,K] @ W[K,N] (+ bias) ----------------
// Requires M%64==0, N%64==0, K%16==0, all pointers 16B aligned.
#define BM 64
#define BN 64
#define BK 16
__global__ void __launch_bounds__(256) gemm_tiled(
    float* __restrict__ C, const float* __restrict__ A, const float* __restrict__ W,
    const float* __restrict__ bias, const float* __restrict__ res, int M, int N, int K)
{
    __shared__ float As[BK][BM + 4];
    __shared__ float Ws[BK][BN];
    int n0 = blockIdx.x * BN, m0 = blockIdx.y * BM;
    int tid = threadIdx.x;
    int tx = tid & 15, ty = tid >> 4;          // 16x16 thread grid, 4x4 regs each
    float c[4][4] = {};
    for (int k0 = 0; k0 < K; k0 += BK) {
        // load A tile (BM x BK), store k-major
        {
            int arow = tid >> 2, acol = (tid & 3) * 4;
            float4 v = *(const float4*)&A[(size_t)(m0 + arow) * K + k0 + acol];
            As[acol + 0][arow] = v.x; As[acol + 1][arow] = v.y;
            As[acol + 2][arow] = v.z; As[acol + 3][arow] = v.w;
        }
        // load W tile (BK x BN)
        {
            int wrow = tid >> 4, wcol = (tid & 15) * 4;
            float4 v = *(const float4*)&W[(size_t)(k0 + wrow) * N + n0 + wcol];
            *(float4*)&Ws[wrow][wcol] = v;
        }
        __syncthreads();
#pragma unroll
        for (int kk = 0; kk < BK; kk++) {
            float4 af = *(const float4*)&As[kk][ty * 4];
            float4 bf = *(const float4*)&Ws[kk][tx * 4];
            float a4[4] = {af.x, af.y, af.z, af.w};
            float b4[4] = {bf.x, bf.y, bf.z, bf.w};
#pragma unroll
            for (int i = 0; i < 4; i++)
#pragma unroll
                for (int j = 0; j < 4; j++) c[i][j] = fmaf(a4[i], b4[j], c[i][j]);
        }
        __syncthreads();
    }
#pragma unroll
    for (int i = 0; i < 4; i++) {
        int row = m0 + ty * 4 + i, col = n0 + tx * 4;
        float4 o;
        float* po = &o.x;
#pragma unroll
        for (int j = 0; j < 4; j++) {
            float v = c[i][j];
            if (bias) v += bias[col + j];
            if (res)  v += res[(size_t)row * N + col + j];
            po[j] = v;
        }
        *(float4*)&C[(size_t)row * N + col] = o;
    }
}

// ---------------- small gathered projection: C[b,i,:] = A[b*T + i*chunk, :] @ W ----------------
__global__ void proj_gather(float* __restrict__ C, const float* __restrict__ A,
                            const float* __restrict__ W, int nUpd, int chunk)
{
    int row = blockIdx.x;                 // b*nUpd + i
    int b = row / nUpd, i = row % nUpd;
    const float* a = A + (size_t)(b * T_ + i * chunk) * D_;
    int nn = threadIdx.x;                 // 192
    float s = 0.f;
#pragma unroll 4
    for (int kk = 0; kk < D_; kk++) s = fmaf(a[kk], W[kk * D_ + nn], s);
    C[(size_t)row * D_ + nn] = s;
}

// ---------------- err recurrence: err_i = v_i - sum_{j<i} cd[i-1-j] * (k_i . k_j) * err_j ----------------
__global__ void rec_kernel(float* __restrict__ ERR, const float* __restrict__ Kmat,
                           const float* __restrict__ Vmat, int n)
{
    __shared__ float G[32][32];
    __shared__ float cd[32];
    __shared__ float serr[32][D_];
    int b = blockIdx.x, e = threadIdx.x;  // 192 threads
    if (e == 0) make_cd(cd, 32);
    for (int p = e; p < n * n; p += D_) {
        int i = p % n, j = p / n;
        if (j < i) {
            const float* kj = Kmat + (size_t)(b * n + j) * D_;
            const float* ki = Kmat + (size_t)(b * n + i) * D_;
            float s = 0.f;
            for (int kk = 0; kk < D_; kk++) s = fmaf(kj[kk], ki[kk], s);
            G[j][i] = s;
        }
    }
    __syncthreads();
    for (int i = 0; i < n; i++) {
        float s = Vmat[(size_t)(b * n + i) * D_ + e];
        for (int j = 0; j < i; j++) s -= cd[i - 1 - j] * G[j][i] * serr[j][e];
        serr[i][e] = s;
        ERR[(size_t)(b * n + i) * D_ + e] = s;
    }
}

// ---------------- QK: QK[b,t,j] = Q[b,t,:] . K[b,j,:] ----------------
__global__ void qk_kernel(float* __restrict__ QK, const float* __restrict__ Q,
                          const float* __restrict__ Kmat, int n)
{
    __shared__ float sKT[D_][33];
    int b = blockIdx.x, t0 = blockIdx.y * 32;
    for (int p = threadIdx.x; p < n * D_; p += 256) {
        int j = p / D_, kk = p % D_;
        sKT[kk][j] = Kmat[(size_t)(b * n + j) * D_ + kk];
    }
    __syncthreads();
    int outs = 32 * n;
    for (int o = threadIdx.x; o < outs; o += 256) {
        int j = o % n, tl = o / n;
        const float* q = Q + (size_t)(b * T_ + t0 + tl) * D_;
        float s = 0.f;
#pragma unroll 4
        for (int kk = 0; kk < D_; kk++) s = fmaf(q[kk], sKT[kk][j], s);
        QK[(size_t)(b * T_ + t0 + tl) * n + j] = s;
    }
}

// ---------------- x1 = xp + 0.5 * delta retrieval ----------------
__global__ void x1_kernel(float* __restrict__ x1, const float* __restrict__ xp,
                          const float* __restrict__ QKd, const float* __restrict__ errd)
{
    int idx = blockIdx.x * blockDim.x + threadIdx.x;
    if (idx >= B_ * T_ * D_) return;
    int e = idx % D_, bt = idx / D_;
    int t = bt % T_, b = bt / T_;
    int r = t >> 6;                       // t / 64
    float cdl[ND_];
    { double ap = 1.0, ep = 1.0;
      for (int d = 0; d < ND_; d++) { ap *= 0.99; ep *= 0.9; cdl[d] = (float)(0.1 * (ap - ep) / 0.09); } }
    float s = 0.f;
    for (int j = 0; j <= r; j++)
        s = fmaf(cdl[r - j] * QKd[bt * ND_ + j], errd[(size_t)(b * ND_ + j) * D_ + e], s);
    x1[idx] = xp[idx] + 0.5f * s;
}

// ---------------- LayerNorm over last dim (192), one block per row ----------------
__global__ void ln_kernel(float* __restrict__ out, const float* __restrict__ in,
                          const float* __restrict__ g, const float* __restrict__ bta)
{
    int row = blockIdx.x, e = threadIdx.x;
    float v = in[(size_t)row * D_ + e];
    float s = v, s2 = v * v;
    for (int o = 16; o > 0; o >>= 1) {
        s  += __shfl_xor_sync(~0u, s,  o);
        s2 += __shfl_xor_sync(~0u, s2, o);
    }
    __shared__ float red[2][6];
    int w = e >> 5, l = e & 31;
    if (l == 0) { red[0][w] = s; red[1][w] = s2; }
    __syncthreads();
    if (e == 0) {
        float ts = 0.f, ts2 = 0.f;
        for (int i = 0; i < 6; i++) { ts += red[0][i]; ts2 += red[1][i]; }
        float m = ts / D_;
        red[0][0] = m;
        red[1][0] = ts2 / D_ - m * m;
    }
    __syncthreads();
    float m = red[0][0], var = red[1][0];
    out[(size_t)row * D_ + e] = (v - m) * rsqrtf(var + EPS_) * g[e] + bta[e];
}

// ---------------- GLU + depthwise tap + BN + SiLU ----------------
__global__ void glu_kernel(float* __restrict__ out, const float* __restrict__ hh,
                           const float* __restrict__ dw, const float* __restrict__ db,
                           const float* __restrict__ bs, const float* __restrict__ bb)
{
    int idx = blockIdx.x * blockDim.x + threadIdx.x;
    if (idx >= B_ * T_ * D_) return;
    int e = idx % D_, row = idx / D_;
    float a = hh[(size_t)row * D2_ + e];
    float g = hh[(size_t)row * D2_ + D_ + e];
    float h = a * (1.f / (1.f + expf(-g)));
    h = h * dw[e] + db[e];
    h = h * bs[e] + bb[e];
    h = h * (1.f / (1.f + expf(-h)));     // silu
    out[idx] = h;
}

// ---------------- x4 = x3 + 0.5 * theta retrieval; LN2 -> y ----------------
__global__ void final_kernel(float* __restrict__ y, const float* __restrict__ x3,
                             const float* __restrict__ QKt, const float* __restrict__ errt,
                             const float* __restrict__ g2, const float* __restrict__ b2)
{
    __shared__ float alpha[32];
    __shared__ float cd[32];
    __shared__ float red[2][6];
    int bt = blockIdx.x, e = threadIdx.x;
    int t = bt % T_, b = bt / T_;
    int r = t >> 3;                       // t / 8
    if (e == 0) make_cd(cd, 32);
    __syncthreads();
    if (e < 32) alpha[e] = (e <= r) ? cd[r - e] * QKt[bt * NT_ + e] : 0.f;
    __syncthreads();
    float s = 0.f;
    for (int j = 0; j <= r; j++)
        s = fmaf(alpha[j], errt[(size_t)(b * NT_ + j) * D_ + e], s);
    float x4 = x3[(size_t)bt * D_ + e] + 0.5f * s;

    float sm = x4, s2 = x4 * x4;
    for (int o = 16; o > 0; o >>= 1) {
        sm += __shfl_xor_sync(~0u, sm, o);
        s2 += __shfl_xor_sync(~0u, s2, o);
    }
    int w = e >> 5, l = e & 31;
    if (l == 0) { red[0][w] = sm; red[1][w] = s2; }
    __syncthreads();
    if (e == 0) {
        float ts = 0.f, ts2 = 0.f;
        for (int i = 0; i < 6; i++) { ts += red[0][i]; ts2 += red[1][i]; }
        float m = ts / D_;
        red[0][0] = m;
        red[1][0] = ts2 / D_ - m * m;
    }
    __syncthreads();
    float m = red[0][0], var = red[1][0];
    y[(size_t)bt * D_ + e] = (x4 - m) * rsqrtf(var + EPS_) * g2[e] + b2[e];
}

// ---------------- mean-pool over T ----------------
__global__ void pool_kernel(float* __restrict__ pool, const float* __restrict__ y)
{
    int idx = blockIdx.x * blockDim.x + threadIdx.x; // b*D + e
    if (idx >= B_ * D_) return;
    int e = idx % D_, b = idx / D_;
    float s = 0.f;
    for (int t = 0; t < T_; t++) s += y[(size_t)(b * T_ + t) * D_ + e];
    pool[idx] = s * (1.f / T_);
}

// ---------------- final projection: out[b,c] = pool[b,:] @ Wc + bc ----------------
__global__ void out_kernel(float* __restrict__ out, const float* __restrict__ pool,
                           const float* __restrict__ Wc, const float* __restrict__ bc)
{
    int idx = threadIdx.x;                // 160
    if (idx >= B_ * NC_) return;
    int c = idx % NC_, b = idx / NC_;
    float s = bc[c];
    for (int e = 0; e < D_; e++) s = fmaf(pool[b * D_ + e], Wc[e * NC_ + c], s);
    out[idx] = s;
}

// =====================================================================
extern "C" void kernel_launch(void* const* d_in, const int* in_sizes, int n_in,
                              void* d_out, int out_size)
{
    const float* x     = (const float*)d_in[0];
    const float* W_in  = (const float*)d_in[1];
    const float* b_in  = (const float*)d_in[2];
    const float* Wv_a  = (const float*)d_in[3];
    const float* bv_a  = (const float*)d_in[4];
    const float* Wo_a  = (const float*)d_in[5];
    const float* bo_a  = (const float*)d_in[6];
    const float* ln1_g = (const float*)d_in[7];
    const float* ln1_b = (const float*)d_in[8];
    const float* pw1_w = (const float*)d_in[9];
    const float* pw1_b = (const float*)d_in[10];
    const float* dw_w  = (const float*)d_in[11];
    const float* dw_b  = (const float*)d_in[12];
    const float* bn_s  = (const float*)d_in[13];
    const float* bn_b  = (const float*)d_in[14];
    const float* pw2_w = (const float*)d_in[15];
    const float* pw2_b = (const float*)d_in[16];
    const float* Wk_t  = (const float*)d_in[17];
    const float* Wv_t  = (const float*)d_in[18];
    const float* Wq_t  = (const float*)d_in[19];
    const float* Wk_d  = (const float*)d_in[20];
    const float* Wv_d  = (const float*)d_in[21];
    const float* Wq_d  = (const float*)d_in[22];
    const float* ln2_g = (const float*)d_in[23];
    const float* ln2_b = (const float*)d_in[24];
    const float* Wc    = (const float*)d_in[25];
    const float* bc    = (const float*)d_in[26];
    float* out = (float*)d_out;

    float *xp, *qd, *x1, *x2, *h, *g2, *x3, *q3, *y, *tmp;
    float *Kd, *Vd, *Ed, *QKd, *Kt, *Vt, *Et, *QKt, *pool;
    cudaGetSymbolAddress((void**)&xp,  g_xp);
    cudaGetSymbolAddress((void**)&qd,  g_qd);
    cudaGetSymbolAddress((void**)&x1,  g_x1);
    cudaGetSymbolAddress((void**)&x2,  g_x2);
    cudaGetSymbolAddress((void**)&h,   g_h);
    cudaGetSymbolAddress((void**)&g2,  g_g2);
    cudaGetSymbolAddress((void**)&x3,  g_x3);
    cudaGetSymbolAddress((void**)&q3,  g_q3);
    cudaGetSymbolAddress((void**)&y,   g_y);
    cudaGetSymbolAddress((void**)&tmp, g_tmp);
    cudaGetSymbolAddress((void**)&Kd,  g_Kd);
    cudaGetSymbolAddress((void**)&Vd,  g_Vd);
    cudaGetSymbolAddress((void**)&Ed,  g_Ed);
    cudaGetSymbolAddress((void**)&QKd, g_QKd);
    cudaGetSymbolAddress((void**)&Kt,  g_Kt);
    cudaGetSymbolAddress((void**)&Vt,  g_Vt);
    cudaGetSymbolAddress((void**)&Et,  g_Et);
    cudaGetSymbolAddress((void**)&QKt, g_QKt);
    cudaGetSymbolAddress((void**)&pool, g_pool);

    const int M = B_ * T_;                      // 2048
    dim3 blk256(256);

    // 1) xp = x @ W_in + b_in
    gemm_tiled<<<dim3(D_ / BN, M / BM), blk256>>>(xp, x, W_in, b_in, nullptr, M, D_, MEL_);
    // 2) qd = xp @ Wq_d
    gemm_tiled<<<dim3(D_ / BN, M / BM), blk256>>>(qd, xp, Wq_d, nullptr, nullptr, M, D_, D_);
    // 3) delta K/V at t in {0,64,128,192}
    proj_gather<<<B_ * ND_, D_>>>(Kd, xp, Wk_d, ND_, 64);
    proj_gather<<<B_ * ND_, D_>>>(Vd, xp, Wv_d, ND_, 64);
    // 4) delta err recurrence
    rec_kernel<<<B_, D_>>>(Ed, Kd, Vd, ND_);
    // 5) QKd[b,t,j]
    qk_kernel<<<dim3(B_, T_ / 32), blk256>>>(QKd, qd, Kd, ND_);
    // 6) x1 = xp + 0.5*d_out
    x1_kernel<<<(M * D_ + 255) / 256, blk256>>>(x1, xp, QKd, Ed);
    // 7) attn: tmp = x1@Wv_a + bv;  x2 = x1 + tmp@Wo_a + bo
    gemm_tiled<<<dim3(D_ / BN, M / BM), blk256>>>(tmp, x1, Wv_a, bv_a, nullptr, M, D_, D_);
    gemm_tiled<<<dim3(D_ / BN, M / BM), blk256>>>(x2, tmp, Wo_a, bo_a, x1, M, D_, D_);
    // 8) conformer conv module
    ln_kernel<<<M, D_>>>(h, x2, ln1_g, ln1_b);
    gemm_tiled<<<dim3(D2_ / BN, M / BM), blk256>>>(tmp, h, pw1_w, pw1_b, nullptr, M, D2_, D_);
    glu_kernel<<<(M * D_ + 255) / 256, blk256>>>(g2, tmp, dw_w, dw_b, bn_s, bn_b);
    gemm_tiled<<<dim3(D_ / BN, M / BM), blk256>>>(x3, g2, pw2_w, pw2_b, x2, M, D_, D_);
    // 9) theta path
    gemm_tiled<<<dim3(D_ / BN, M / BM), blk256>>>(q3, x3, Wq_t, nullptr, nullptr, M, D_, D_);
    proj_gather<<<B_ * NT_, D_>>>(Kt, x3, Wk_t, NT_, 8);
    proj_gather<<<B_ * NT_, D_>>>(Vt, x3, Wv_t, NT_, 8);
    rec_kernel<<<B_, D_>>>(Et, Kt, Vt, NT_);
    qk_kernel<<<dim3(B_, T_ / 32), blk256>>>(QKt, q3, Kt, NT_);
    // 10) x4 + LN2 -> y
    final_kernel<<<M, D_>>>(y, x3, QKt, Et, ln2_g, ln2_b);
    // 11) pool + classifier
    pool_kernel<<<(B_ * D_ + 255) / 256, blk256>>>(pool, y);
    out_kernel<<<1, 256>>>(out, pool, Wc, bc);
}

// round 3
// speedup vs baseline: 1.7069x; 1.7069x over previous
#include <cuda_runtime.h>
#include <math.h>

// ---------------- problem constants ----------------
#define B_  8
#define T_  256
#define MEL_ 128
#define D_  192
#define NC_ 20
#define D2_ 384
#define NT_ 32     // theta updates  (chunk 8)
#define ND_ 4      // delta updates  (chunk 64)
#define EPS_ 1e-5f

// ---------------- scratch ----------------
__device__ float g_xp [B_*T_*D_];
__device__ float g_qd [B_*T_*D_];
__device__ float g_x1 [B_*T_*D_];
__device__ float g_x2 [B_*T_*D_];
__device__ float g_h  [B_*T_*D_];
__device__ float g_g2 [B_*T_*D_];
__device__ float g_x3 [B_*T_*D_];
__device__ float g_q3 [B_*T_*D_];
__device__ float g_y  [B_*T_*D_];
__device__ float g_Kd [B_*ND_*D_];
__device__ float g_Vd [B_*ND_*D_];
__device__ float g_Ed [B_*ND_*D_];
__device__ float g_Kt [B_*NT_*D_];
__device__ float g_Vt [B_*NT_*D_];
__device__ float g_Et [B_*NT_*D_];
__device__ float g_Wao[D_*D_];
__device__ float g_bao[D_];

// coefficient c_d = LR * (a^{d+1} - e^{d+1}) / (a - e), a=0.99, e=0.9
__device__ __forceinline__ void make_cd(float* cd, int n) {
    double ap = 1.0, ep = 1.0;
    for (int d = 0; d < n; d++) { ap *= 0.99; ep *= 0.9; cd[d] = (float)(0.1 * (ap - ep) / 0.09); }
}

// ---------------- tiled GEMM: C[M,N] = (res?) + A[M,K] @ W[K,N] (+ bias) ----------------
#define BM 64
#define BN 64
#define BK 16
__global__ void __launch_bounds__(256) gemm_tiled(
    float* __restrict__ C, const float* __restrict__ A, const float* __restrict__ W,
    const float* __restrict__ bias, const float* __restrict__ res, int M, int N, int K)
{
    __shared__ float As[BK][BM + 4];
    __shared__ float Ws[BK][BN];
    int n0 = blockIdx.x * BN, m0 = blockIdx.y * BM;
    int tid = threadIdx.x;
    int tx = tid & 15, ty = tid >> 4;
    float c[4][4] = {};
    for (int k0 = 0; k0 < K; k0 += BK) {
        {
            int arow = tid >> 2, acol = (tid & 3) * 4;
            float4 v = *(const float4*)&A[(size_t)(m0 + arow) * K + k0 + acol];
            As[acol + 0][arow] = v.x; As[acol + 1][arow] = v.y;
            As[acol + 2][arow] = v.z; As[acol + 3][arow] = v.w;
        }
        {
            int wrow = tid >> 4, wcol = (tid & 15) * 4;
            float4 v = *(const float4*)&W[(size_t)(k0 + wrow) * N + n0 + wcol];
            *(float4*)&Ws[wrow][wcol] = v;
        }
        __syncthreads();
#pragma unroll
        for (int kk = 0; kk < BK; kk++) {
            float4 af = *(const float4*)&As[kk][ty * 4];
            float4 bf = *(const float4*)&Ws[kk][tx * 4];
            float a4[4] = {af.x, af.y, af.z, af.w};
            float b4[4] = {bf.x, bf.y, bf.z, bf.w};
#pragma unroll
            for (int i = 0; i < 4; i++)
#pragma unroll
                for (int j = 0; j < 4; j++) c[i][j] = fmaf(a4[i], b4[j], c[i][j]);
        }
        __syncthreads();
    }
#pragma unroll
    for (int i = 0; i < 4; i++) {
        int row = m0 + ty * 4 + i, col = n0 + tx * 4;
        float4 o;
        float* po = &o.x;
#pragma unroll
        for (int j = 0; j < 4; j++) {
            float v = c[i][j];
            if (bias) v += bias[col + j];
            if (res)  v += res[(size_t)row * N + col + j];
            po[j] = v;
        }
        *(float4*)&C[(size_t)row * N + col] = o;
    }
}

// ---------------- GEMM (N=384) with fused GLU + dw + BN + SiLU epilogue -> out [M,192] ----------------
__global__ void __launch_bounds__(256) gemm_glu(
    float* __restrict__ out, const float* __restrict__ A, const float* __restrict__ W,
    const float* __restrict__ bias,
    const float* __restrict__ dw, const float* __restrict__ db,
    const float* __restrict__ bs, const float* __restrict__ bb, int M, int K)
{
    __shared__ float As[BK][BM + 4];
    __shared__ float Wsa[BK][BN];
    __shared__ float Wsg[BK][BN];
    int n0 = blockIdx.x * BN, m0 = blockIdx.y * BM;
    int tid = threadIdx.x;
    int tx = tid & 15, ty = tid >> 4;
    float cA[4][4] = {}, cG[4][4] = {};
    for (int k0 = 0; k0 < K; k0 += BK) {
        {
            int arow = tid >> 2, acol = (tid & 3) * 4;
            float4 v = *(const float4*)&A[(size_t)(m0 + arow) * K + k0 + acol];
            As[acol + 0][arow] = v.x; As[acol + 1][arow] = v.y;
            As[acol + 2][arow] = v.z; As[acol + 3][arow] = v.w;
        }
        {
            int wrow = tid >> 4, wcol = (tid & 15) * 4;
            float4 va = *(const float4*)&W[(size_t)(k0 + wrow) * D2_ + n0 + wcol];
            float4 vg = *(const float4*)&W[(size_t)(k0 + wrow) * D2_ + D_ + n0 + wcol];
            *(float4*)&Wsa[wrow][wcol] = va;
            *(float4*)&Wsg[wrow][wcol] = vg;
        }
        __syncthreads();
#pragma unroll
        for (int kk = 0; kk < BK; kk++) {
            float4 af = *(const float4*)&As[kk][ty * 4];
            float4 ba = *(const float4*)&Wsa[kk][tx * 4];
            float4 bg = *(const float4*)&Wsg[kk][tx * 4];
            float a4[4] = {af.x, af.y, af.z, af.w};
            float ba4[4] = {ba.x, ba.y, ba.z, ba.w};
            float bg4[4] = {bg.x, bg.y, bg.z, bg.w};
#pragma unroll
            for (int i = 0; i < 4; i++)
#pragma unroll
                for (int j = 0; j < 4; j++) {
                    cA[i][j] = fmaf(a4[i], ba4[j], cA[i][j]);
                    cG[i][j] = fmaf(a4[i], bg4[j], cG[i][j]);
                }
        }
        __syncthreads();
    }
#pragma unroll
    for (int i = 0; i < 4; i++) {
        int row = m0 + ty * 4 + i, col = n0 + tx * 4;
        float4 o;
        float* po = &o.x;
#pragma unroll
        for (int j = 0; j < 4; j++) {
            float a = cA[i][j] + bias[col + j];
            float g = cG[i][j] + bias[D_ + col + j];
            float h = a * (1.f / (1.f + expf(-g)));
            h = h * dw[col + j] + db[col + j];
            h = h * bs[col + j] + bb[col + j];
            h = h * (1.f / (1.f + expf(-h)));
            po[j] = h;
        }
        *(float4*)&out[(size_t)row * D_ + col] = o;
    }
}

// ---------------- precompute Wao = Wv_a @ Wo_a ; bao = bv_a @ Wo_a + bo_a ----------------
__global__ void __launch_bounds__(256) prep_attn(
    float* __restrict__ Wao, float* __restrict__ bao,
    const float* __restrict__ Wv, const float* __restrict__ Wo,
    const float* __restrict__ bv, const float* __restrict__ bo)
{
    if (blockIdx.y == 3) {
        if (blockIdx.x != 0) return;
        int n = threadIdx.x;
        if (n >= D_) return;
        float s = bo[n];
#pragma unroll 8
        for (int e = 0; e < D_; e++) s = fmaf(bv[e], Wo[e * D_ + n], s);
        bao[n] = s;
        return;
    }
    __shared__ float As[BK][BM + 4];
    __shared__ float Ws[BK][BN];
    int n0 = blockIdx.x * BN, m0 = blockIdx.y * BM;
    int tid = threadIdx.x;
    int tx = tid & 15, ty = tid >> 4;
    float c[4][4] = {};
    for (int k0 = 0; k0 < D_; k0 += BK) {
        {
            int arow = tid >> 2, acol = (tid & 3) * 4;
            float4 v = *(const float4*)&Wv[(size_t)(m0 + arow) * D_ + k0 + acol];
            As[acol + 0][arow] = v.x; As[acol + 1][arow] = v.y;
            As[acol + 2][arow] = v.z; As[acol + 3][arow] = v.w;
        }
        {
            int wrow = tid >> 4, wcol = (tid & 15) * 4;
            float4 v = *(const float4*)&Wo[(size_t)(k0 + wrow) * D_ + n0 + wcol];
            *(float4*)&Ws[wrow][wcol] = v;
        }
        __syncthreads();
#pragma unroll
        for (int kk = 0; kk < BK; kk++) {
            float4 af = *(const float4*)&As[kk][ty * 4];
            float4 bf = *(const float4*)&Ws[kk][tx * 4];
            float a4[4] = {af.x, af.y, af.z, af.w};
            float b4[4] = {bf.x, bf.y, bf.z, bf.w};
#pragma unroll
            for (int i = 0; i < 4; i++)
#pragma unroll
                for (int j = 0; j < 4; j++) c[i][j] = fmaf(a4[i], b4[j], c[i][j]);
        }
        __syncthreads();
    }
#pragma unroll
    for (int i = 0; i < 4; i++) {
        int row = m0 + ty * 4 + i, col = n0 + tx * 4;
        float4 o = {c[i][0], c[i][1], c[i][2], c[i][3]};
        *(float4*)&Wao[(size_t)row * D_ + col] = o;
    }
}

// ---------------- fused K+V gathered projection (row of A staged in smem, deep unroll) ----------------
__global__ void projKV(float* __restrict__ Ko, float* __restrict__ Vo,
                       const float* __restrict__ A,
                       const float* __restrict__ Wk, const float* __restrict__ Wv,
                       int nUpd, int chunk)
{
    __shared__ float sa[D_];
    int row = blockIdx.x;                 // b*nUpd + i
    int b = row / nUpd, i = row % nUpd;
    int nn = threadIdx.x;
    sa[nn] = A[(size_t)(b * T_ + i * chunk) * D_ + nn];
    __syncthreads();
    float sk = 0.f, sv = 0.f;
#pragma unroll 8
    for (int kk = 0; kk < D_; kk++) {
        float a = sa[kk];
        sk = fmaf(a, Wk[kk * D_ + nn], sk);
        sv = fmaf(a, Wv[kk * D_ + nn], sv);
    }
    Ko[(size_t)row * D_ + nn] = sk;
    Vo[(size_t)row * D_ + nn] = sv;
}

// ---------------- err recurrence (smem Gram, register err chain) ----------------
template<int N>
__global__ void __launch_bounds__(256) rec_kernel(
    float* __restrict__ ERR, const float* __restrict__ Kmat, const float* __restrict__ Vmat)
{
    __shared__ float sK[N][D_ + 1];
    __shared__ float G[N][N];
    int b = blockIdx.x, tid = threadIdx.x;
    for (int idx = tid; idx < N * D_; idx += 256) {
        int r = idx / D_, c = idx % D_;
        sK[r][c] = Kmat[(size_t)(b * N + r) * D_ + c];
    }
    __syncthreads();
    // Gram: pairs j<i
    const int NP = N * (N - 1) / 2;
    for (int p = tid; p < NP; p += 256) {
        int i = (int)((1.0f + sqrtf(1.0f + 8.0f * (float)p)) * 0.5f);
        while (i * (i - 1) / 2 > p) i--;
        while ((i + 1) * i / 2 <= p) i++;
        int j = p - i * (i - 1) / 2;
        float s = 0.f;
#pragma unroll 8
        for (int kk = 0; kk < D_; kk++) s = fmaf(sK[j][kk], sK[i][kk], s);
        G[j][i] = s;
    }
    __syncthreads();
    if (tid < D_) {
        int e = tid;
        float cdl[N];
        {
            double ap = 1.0, ep = 1.0;
#pragma unroll
            for (int d = 0; d < N; d++) { ap *= 0.99; ep *= 0.9; cdl[d] = (float)(0.1 * (ap - ep) / 0.09); }
        }
        float err[N];
#pragma unroll
        for (int i = 0; i < N; i++) {
            float s = Vmat[(size_t)(b * N + i) * D_ + e];
#pragma unroll
            for (int j = 0; j < i; j++) s -= cdl[i - 1 - j] * G[j][i] * err[j];
            err[i] = s;
            ERR[(size_t)(b * N + i) * D_ + e] = s;
        }
    }
}

// ---------------- fused delta QK + x1 = xp + 0.5*retrieval (block per (b,t)) ----------------
__global__ void __launch_bounds__(192) qkx1_kernel(
    float* __restrict__ x1, const float* __restrict__ xp, const float* __restrict__ qd,
    const float* __restrict__ Kd, const float* __restrict__ Ed)
{
    __shared__ float sK[ND_][D_];
    __shared__ float sE[ND_][D_];
    __shared__ float red[ND_][6];
    __shared__ float alpha[ND_];
    int bt = blockIdx.x;
    int b = bt / T_, t = bt % T_, r = t >> 6;
    int e = threadIdx.x;
#pragma unroll
    for (int j = 0; j < ND_; j++) {
        sK[j][e] = Kd[(size_t)(b * ND_ + j) * D_ + e];
        sE[j][e] = Ed[(size_t)(b * ND_ + j) * D_ + e];
    }
    __syncthreads();
    float q = qd[(size_t)bt * D_ + e];
    float p[ND_];
#pragma unroll
    for (int j = 0; j < ND_; j++) p[j] = q * sK[j][e];
#pragma unroll
    for (int o = 16; o > 0; o >>= 1)
#pragma unroll
        for (int j = 0; j < ND_; j++) p[j] += __shfl_xor_sync(~0u, p[j], o);
    int w = e >> 5, l = e & 31;
    if (l == 0)
#pragma unroll
        for (int j = 0; j < ND_; j++) red[j][w] = p[j];
    __syncthreads();
    if (e < ND_) {
        float s = 0.f;
#pragma unroll
        for (int w2 = 0; w2 < 6; w2++) s += red[e][w2];
        float cdl[ND_];
        double ap = 1.0, ep = 1.0;
#pragma unroll
        for (int d = 0; d < ND_; d++) { ap *= 0.99; ep *= 0.9; cdl[d] = (float)(0.1 * (ap - ep) / 0.09); }
        alpha[e] = (e <= r) ? cdl[r - e] * s : 0.f;
    }
    __syncthreads();
    float s = 0.f;
#pragma unroll
    for (int j = 0; j < ND_; j++) s = fmaf(alpha[j], sE[j][e], s);
    x1[(size_t)bt * D_ + e] = xp[(size_t)bt * D_ + e] + 0.5f * s;
}

// ---------------- fused theta QK + x4 + LN2 -> y (block per 8 t's of one b) ----------------
#define TC_ 8
__global__ void __launch_bounds__(192) qkfinal_kernel(
    float* __restrict__ y, const float* __restrict__ x3, const float* __restrict__ q3,
    const float* __restrict__ Kt, const float* __restrict__ Et,
    const float* __restrict__ g2, const float* __restrict__ b2)
{
    __shared__ float sKT[D_][NT_ + 1];   // [e][j]
    __shared__ float red[NT_][6];
    __shared__ float alpha[NT_];
    __shared__ float cdS[NT_];
    __shared__ float lred[2][6];
    int blk = blockIdx.x;
    int b = blk / (T_ / TC_), tc = blk % (T_ / TC_);
    int t0 = tc * TC_;
    int tid = threadIdx.x;
    if (tid == 0) make_cd(cdS, NT_);
    for (int idx = tid; idx < NT_ * D_; idx += 192) {
        int j = idx / D_, e2 = idx % D_;
        sKT[e2][j] = Kt[(size_t)(b * NT_ + j) * D_ + e2];
    }
    __syncthreads();
    int j = tid & 31, g = tid >> 5;       // 32 j x 6 e-groups
    for (int tt = 0; tt < TC_; tt++) {
        int t = t0 + tt, row = b * T_ + t, r = t >> 3;
        // partial dot over e-range of this group
        float part = 0.f;
        const float* qr = q3 + (size_t)row * D_;
#pragma unroll
        for (int u = 0; u < 32; u++) {
            int e2 = g * 32 + u;
            part = fmaf(qr[e2], sKT[e2][j], part);
        }
        red[j][g] = part;
        __syncthreads();
        if (tid < NT_) {
            float s = 0.f;
#pragma unroll
            for (int g2i = 0; g2i < 6; g2i++) s += red[tid][g2i];
            alpha[tid] = (tid <= r) ? cdS[r - tid] * s : 0.f;
        }
        __syncthreads();
        int e = tid;
        float s = 0.f;
        for (int jj = 0; jj <= r; jj++)
            s = fmaf(alpha[jj], Et[(size_t)(b * NT_ + jj) * D_ + e], s);
        float x4 = x3[(size_t)row * D_ + e] + 0.5f * s;
        // LayerNorm
        float sm = x4, s2 = x4 * x4;
#pragma unroll
        for (int o = 16; o > 0; o >>= 1) {
            sm += __shfl_xor_sync(~0u, sm, o);
            s2 += __shfl_xor_sync(~0u, s2, o);
        }
        int w = e >> 5, l = e & 31;
        if (l == 0) { lred[0][w] = sm; lred[1][w] = s2; }
        __syncthreads();
        float ts = 0.f, ts2 = 0.f;
#pragma unroll
        for (int i = 0; i < 6; i++) { ts += lred[0][i]; ts2 += lred[1][i]; }
        float m = ts / D_;
        float var = ts2 / D_ - m * m;
        y[(size_t)row * D_ + e] = (x4 - m) * rsqrtf(var + EPS_) * g2[e] + b2[e];
        __syncthreads();
    }
}

// ---------------- LayerNorm over last dim (192), one block per row ----------------
__global__ void __launch_bounds__(192) ln_kernel(
    float* __restrict__ out, const float* __restrict__ in,
    const float* __restrict__ g, const float* __restrict__ bta)
{
    int row = blockIdx.x, e = threadIdx.x;
    float v = in[(size_t)row * D_ + e];
    float s = v, s2 = v * v;
#pragma unroll
    for (int o = 16; o > 0; o >>= 1) {
        s  += __shfl_xor_sync(~0u, s,  o);
        s2 += __shfl_xor_sync(~0u, s2, o);
    }
    __shared__ float red[2][6];
    int w = e >> 5, l = e & 31;
    if (l == 0) { red[0][w] = s; red[1][w] = s2; }
    __syncthreads();
    float ts = 0.f, ts2 = 0.f;
#pragma unroll
    for (int i = 0; i < 6; i++) { ts += red[0][i]; ts2 += red[1][i]; }
    float m = ts / D_;
    float var = ts2 / D_ - m * m;
    out[(size_t)row * D_ + e] = (v - m) * rsqrtf(var + EPS_) * g[e] + bta[e];
}

// ---------------- pool over T + classifier ----------------
__global__ void __launch_bounds__(768) poolout_kernel(
    float* __restrict__ out, const float* __restrict__ y,
    const float* __restrict__ Wc, const float* __restrict__ bc)
{
    __shared__ float sp[4][D_];
    __shared__ float pooled[D_];
    int b = blockIdx.x, tid = threadIdx.x;
    int e = tid % D_, tq = tid / D_;      // 4 t-slices of 64
    float s = 0.f;
#pragma unroll 8
    for (int t = tq * 64; t < tq * 64 + 64; t++)
        s += y[(size_t)(b * T_ + t) * D_ + e];
    sp[tq][e] = s;
    __syncthreads();
    if (tid < D_) pooled[tid] = (sp[0][tid] + sp[1][tid] + sp[2][tid] + sp[3][tid]) * (1.f / T_);
    __syncthreads();
    if (tid < NC_) {
        int c = tid;
        float acc = bc[c];
#pragma unroll 8
        for (int e2 = 0; e2 < D_; e2++) acc = fmaf(pooled[e2], Wc[e2 * NC_ + c], acc);
        out[b * NC_ + c] = acc;
    }
}

// =====================================================================
extern "C" void kernel_launch(void* const* d_in, const int* in_sizes, int n_in,
                              void* d_out, int out_size)
{
    const float* x     = (const float*)d_in[0];
    const float* W_in  = (const float*)d_in[1];
    const float* b_in  = (const float*)d_in[2];
    const float* Wv_a  = (const float*)d_in[3];
    const float* bv_a  = (const float*)d_in[4];
    const float* Wo_a  = (const float*)d_in[5];
    const float* bo_a  = (const float*)d_in[6];
    const float* ln1_g = (const float*)d_in[7];
    const float* ln1_b = (const float*)d_in[8];
    const float* pw1_w = (const float*)d_in[9];
    const float* pw1_b = (const float*)d_in[10];
    const float* dw_w  = (const float*)d_in[11];
    const float* dw_b  = (const float*)d_in[12];
    const float* bn_s  = (const float*)d_in[13];
    const float* bn_b  = (const float*)d_in[14];
    const float* pw2_w = (const float*)d_in[15];
    const float* pw2_b = (const float*)d_in[16];
    const float* Wk_t  = (const float*)d_in[17];
    const float* Wv_t  = (const float*)d_in[18];
    const float* Wq_t  = (const float*)d_in[19];
    const float* Wk_d  = (const float*)d_in[20];
    const float* Wv_d  = (const float*)d_in[21];
    const float* Wq_d  = (const float*)d_in[22];
    const float* ln2_g = (const float*)d_in[23];
    const float* ln2_b = (const float*)d_in[24];
    const float* Wc    = (const float*)d_in[25];
    const float* bc    = (const float*)d_in[26];
    float* out = (float*)d_out;

    float *xp, *qd, *x1, *x2, *h, *g2, *x3, *q3, *y;
    float *Kd, *Vd, *Ed, *Kt, *Vt, *Et, *Wao, *bao;
    cudaGetSymbolAddress((void**)&xp,  g_xp);
    cudaGetSymbolAddress((void**)&qd,  g_qd);
    cudaGetSymbolAddress((void**)&x1,  g_x1);
    cudaGetSymbolAddress((void**)&x2,  g_x2);
    cudaGetSymbolAddress((void**)&h,   g_h);
    cudaGetSymbolAddress((void**)&g2,  g_g2);
    cudaGetSymbolAddress((void**)&x3,  g_x3);
    cudaGetSymbolAddress((void**)&q3,  g_q3);
    cudaGetSymbolAddress((void**)&y,   g_y);
    cudaGetSymbolAddress((void**)&Kd,  g_Kd);
    cudaGetSymbolAddress((void**)&Vd,  g_Vd);
    cudaGetSymbolAddress((void**)&Ed,  g_Ed);
    cudaGetSymbolAddress((void**)&Kt,  g_Kt);
    cudaGetSymbolAddress((void**)&Vt,  g_Vt);
    cudaGetSymbolAddress((void**)&Et,  g_Et);
    cudaGetSymbolAddress((void**)&Wao, g_Wao);
    cudaGetSymbolAddress((void**)&bao, g_bao);

    const int M = B_ * T_;                      // 2048
    dim3 blk256(256);

    // 0) attention weight fold: Wao = Wv_a@Wo_a, bao = bv_a@Wo_a + bo_a
    prep_attn<<<dim3(3, 4), blk256>>>(Wao, bao, Wv_a, Wo_a, bv_a, bo_a);
    // 1) xp = x @ W_in + b_in
    gemm_tiled<<<dim3(D_ / BN, M / BM), blk256>>>(xp, x, W_in, b_in, nullptr, M, D_, MEL_);
    // 2) delta memory: K/V at t in {0,64,128,192}, err recurrence
    projKV<<<B_ * ND_, D_>>>(Kd, Vd, xp, Wk_d, Wv_d, ND_, 64);
    rec_kernel<ND_><<<B_, 256>>>(Ed, Kd, Vd);
    // 3) qd = xp @ Wq_d
    gemm_tiled<<<dim3(D_ / BN, M / BM), blk256>>>(qd, xp, Wq_d, nullptr, nullptr, M, D_, D_);
    // 4) x1 = xp + 0.5 * delta retrieval  (QK fused)
    qkx1_kernel<<<M, D_>>>(x1, xp, qd, Kd, Ed);
    // 5) x2 = x1 + x1@Wao + bao  (folded attention)
    gemm_tiled<<<dim3(D_ / BN, M / BM), blk256>>>(x2, x1, Wao, bao, x1, M, D_, D_);
    // 6) conformer conv module
    ln_kernel<<<M, D_>>>(h, x2, ln1_g, ln1_b);
    gemm_glu<<<dim3(D_ / BN, M / BM), blk256>>>(g2, h, pw1_w, pw1_b, dw_w, dw_b, bn_s, bn_b, M, D_);
    gemm_tiled<<<dim3(D_ / BN, M / BM), blk256>>>(x3, g2, pw2_w, pw2_b, x2, M, D_, D_);
    // 7) theta memory
    gemm_tiled<<<dim3(D_ / BN, M / BM), blk256>>>(q3, x3, Wq_t, nullptr, nullptr, M, D_, D_);
    projKV<<<B_ * NT_, D_>>>(Kt, Vt, x3, Wk_t, Wv_t, NT_, 8);
    rec_kernel<NT_><<<B_, 256>>>(Et, Kt, Vt);
    // 8) x4 = x3 + 0.5*theta retrieval; LN2 -> y  (QK fused)
    qkfinal_kernel<<<B_ * (T_ / TC_), D_>>>(y, x3, q3, Kt, Et, ln2_g, ln2_b);
    // 9) pool + classifier
    poolout_kernel<<<B_, 768>>>(out, y, Wc, bc);
}